// round 1
// baseline (speedup 1.0000x reference)
#include <cuda_runtime.h>
#include <cstdint>
#include <cstddef>

#define NN   8192
#define EE   262144
#define FEATN 1386
#define HIDN 4096
#define CODEN 64

// ---------------- scratch (no allocation allowed) ----------------
__device__ float g_xt[NN * CODEN];
__device__ float g_m[NN * CODEN];
__device__ float g_Dcnt[NN];
__device__ float g_Bcnt[NN];

// ---------------- helpers ----------------
__device__ __forceinline__ uint32_t f2tf32(float f) {
    uint32_t r;
    asm("cvt.rna.tf32.f32 %0, %1;" : "=r"(r) : "f"(f));
    return r;
}

__device__ __forceinline__ void cp_async16(uint32_t smem, const void* gmem, int src_bytes) {
    asm volatile("cp.async.cg.shared.global [%0], [%1], 16, %2;\n"
                 :: "r"(smem), "l"(gmem), "r"(src_bytes));
}
__device__ __forceinline__ void cp_async8(uint32_t smem, const void* gmem, int src_bytes) {
    asm volatile("cp.async.ca.shared.global [%0], [%1], 8, %2;\n"
                 :: "r"(smem), "l"(gmem), "r"(src_bytes));
}
__device__ __forceinline__ void cp_commit() {
    asm volatile("cp.async.commit_group;\n");
}

__device__ __forceinline__ void mma_tf32(float c[4], const uint32_t a[4], const uint32_t b[2]) {
    asm volatile(
        "mma.sync.aligned.m16n8k8.row.col.f32.tf32.tf32.f32 "
        "{%0,%1,%2,%3}, {%4,%5,%6,%7}, {%8,%9}, {%0,%1,%2,%3};\n"
        : "+f"(c[0]), "+f"(c[1]), "+f"(c[2]), "+f"(c[3])
        : "r"(a[0]), "r"(a[1]), "r"(a[2]), "r"(a[3]), "r"(b[0]), "r"(b[1]));
}

// ---------------- GEMM1: feat = relu(x @ W1 + b1) ----------------
// M=8192, K=1386, N=4096.  BM=128, BN=128, BK=16, 256 threads, TF32 mma.
__global__ __launch_bounds__(256, 1)
void gemm1_kernel(const float* __restrict__ X, const float* __restrict__ W,
                  const float* __restrict__ bias1, float* __restrict__ feat) {
    constexpr int BM = 128, BN = 128, BK = 16;
    constexpr int AS = 20;   // padded smem row stride (floats) for A
    constexpr int BS = 136;  // padded smem row stride (floats) for B
    __shared__ float sA[2][BM * AS];
    __shared__ float sB[2][BK * BS];

    const int tid = threadIdx.x;
    const int m0 = blockIdx.y * BM;
    const int n0 = blockIdx.x * BN;
    const int KT = (FEATN + BK - 1) / BK;   // 87

    // ---- tile loaders ----
    // A: x rows are only 8B-aligned (1386*4 = 5544 B stride) -> 8B cp.async chunks.
    // 128 rows x 16 floats = 1024 chunks of 2 floats; 4 per thread.
    auto loadA = [&](int buf, int k0) {
        #pragma unroll
        for (int i = 0; i < 4; i++) {
            int c   = tid + i * 256;
            int row = c >> 3;
            int cc  = c & 7;
            int kk  = k0 + cc * 2;
            int ok  = (kk < FEATN);
            const float* src = X + (size_t)(m0 + row) * FEATN + (ok ? kk : 0);
            uint32_t dst = (uint32_t)__cvta_generic_to_shared(&sA[buf][row * AS + cc * 2]);
            cp_async8(dst, src, ok ? 8 : 0);  // FEATN even -> no partial 2-float chunk
        }
    };
    // B: W rows 16 KB stride, 16B aligned. 16 rows x 128 floats = 512 16B chunks; 2/thread.
    auto loadB = [&](int buf, int k0) {
        #pragma unroll
        for (int i = 0; i < 2; i++) {
            int c   = tid + i * 256;
            int row = c >> 5;
            int cc  = c & 31;
            int kk  = k0 + row;
            int ok  = (kk < FEATN);
            const float* src = W + (size_t)(ok ? kk : 0) * HIDN + n0 + cc * 4;
            uint32_t dst = (uint32_t)__cvta_generic_to_shared(&sB[buf][row * BS + cc * 4]);
            cp_async16(dst, src, ok ? 16 : 0);
        }
    };

    float acc[4][4][4];
    #pragma unroll
    for (int mi = 0; mi < 4; mi++)
        #pragma unroll
        for (int ni = 0; ni < 4; ni++)
            #pragma unroll
            for (int r = 0; r < 4; r++) acc[mi][ni][r] = 0.f;

    loadA(0, 0); loadB(0, 0); cp_commit();

    const int warp = tid >> 5, lane = tid & 31;
    const int wm = warp & 1, wn = warp >> 1;       // 2 x 4 warp grid
    const int mW = wm * 64, nW = wn * 32;          // warp tile 64 x 32
    const int g = lane >> 2, t = lane & 3;

    int buf = 0;
    for (int kt = 0; kt < KT; kt++) {
        if (kt + 1 < KT) {
            loadA(buf ^ 1, (kt + 1) * BK);
            loadB(buf ^ 1, (kt + 1) * BK);
            cp_commit();
            asm volatile("cp.async.wait_group 1;\n");
        } else {
            asm volatile("cp.async.wait_group 0;\n");
        }
        __syncthreads();

        const float* A = sA[buf];
        const float* B = sB[buf];
        #pragma unroll
        for (int ks = 0; ks < 2; ks++) {
            const int k0s = ks * 8;
            uint32_t af[4][4], bf[4][2];
            #pragma unroll
            for (int mi = 0; mi < 4; mi++) {
                int r = mW + mi * 16;
                af[mi][0] = f2tf32(A[(r + g    ) * AS + k0s + t    ]);
                af[mi][1] = f2tf32(A[(r + g + 8) * AS + k0s + t    ]);
                af[mi][2] = f2tf32(A[(r + g    ) * AS + k0s + t + 4]);
                af[mi][3] = f2tf32(A[(r + g + 8) * AS + k0s + t + 4]);
            }
            #pragma unroll
            for (int ni = 0; ni < 4; ni++) {
                int cc = nW + ni * 8 + g;
                bf[ni][0] = f2tf32(B[(k0s + t    ) * BS + cc]);
                bf[ni][1] = f2tf32(B[(k0s + t + 4) * BS + cc]);
            }
            #pragma unroll
            for (int mi = 0; mi < 4; mi++)
                #pragma unroll
                for (int ni = 0; ni < 4; ni++)
                    mma_tf32(acc[mi][ni], af[mi], bf[ni]);
        }
        __syncthreads();
        buf ^= 1;
    }

    // epilogue: +bias, relu, store
    #pragma unroll
    for (int mi = 0; mi < 4; mi++) {
        #pragma unroll
        for (int ni = 0; ni < 4; ni++) {
            int col = n0 + nW + ni * 8 + t * 2;
            float bv0 = bias1[col], bv1 = bias1[col + 1];
            int r0 = m0 + mW + mi * 16 + g;
            float v0 = fmaxf(acc[mi][ni][0] + bv0, 0.f);
            float v1 = fmaxf(acc[mi][ni][1] + bv1, 0.f);
            *reinterpret_cast<float2*>(&feat[(size_t)r0 * HIDN + col]) = make_float2(v0, v1);
            float v2 = fmaxf(acc[mi][ni][2] + bv0, 0.f);
            float v3 = fmaxf(acc[mi][ni][3] + bv1, 0.f);
            *reinterpret_cast<float2*>(&feat[(size_t)(r0 + 8) * HIDN + col]) = make_float2(v2, v3);
        }
    }
}

// ---------------- GEMM2: xt = feat @ theta  (split-K atomics) ----------------
// M=8192, K=4096, N=64.  BM=128, BN=64, BK=16, split-K = 4.
__global__ __launch_bounds__(256, 1)
void gemm2_kernel(const float* __restrict__ feat, const float* __restrict__ theta) {
    constexpr int BM = 128, BK = 16;
    constexpr int AS = 20, BS = 72;
    constexpr int SPLIT_LEN = 1024;
    __shared__ float sA[2][BM * AS];
    __shared__ float sB[2][BK * BS];

    const int tid = threadIdx.x;
    const int m0 = blockIdx.y * BM;
    const int kbase = blockIdx.x * SPLIT_LEN;
    const int KT = SPLIT_LEN / BK;  // 64

    // A: feat rows 16 KB stride, 16B aligned -> 16B chunks. 128x16 floats = 512 chunks; 2/thread.
    auto loadA = [&](int buf, int k0) {
        #pragma unroll
        for (int i = 0; i < 2; i++) {
            int c   = tid + i * 256;
            int row = c >> 2;
            int cc  = c & 3;
            const float* src = feat + (size_t)(m0 + row) * HIDN + kbase + k0 + cc * 4;
            uint32_t dst = (uint32_t)__cvta_generic_to_shared(&sA[buf][row * AS + cc * 4]);
            cp_async16(dst, src, 16);
        }
    };
    // B: theta rows 256B stride. 16 x 64 floats = 256 chunks; 1/thread.
    auto loadB = [&](int buf, int k0) {
        int row = tid >> 4;
        int cc  = tid & 15;
        const float* src = theta + (size_t)(kbase + k0 + row) * CODEN + cc * 4;
        uint32_t dst = (uint32_t)__cvta_generic_to_shared(&sB[buf][row * BS + cc * 4]);
        cp_async16(dst, src, 16);
    };

    float acc[2][4][4];
    #pragma unroll
    for (int mi = 0; mi < 2; mi++)
        #pragma unroll
        for (int ni = 0; ni < 4; ni++)
            #pragma unroll
            for (int r = 0; r < 4; r++) acc[mi][ni][r] = 0.f;

    loadA(0, 0); loadB(0, 0); cp_commit();

    const int warp = tid >> 5, lane = tid & 31;
    const int wm = warp & 3, wn = warp >> 2;     // 4 x 2 warp grid
    const int mW = wm * 32, nW = wn * 32;        // warp tile 32 x 32
    const int g = lane >> 2, t = lane & 3;

    int buf = 0;
    for (int kt = 0; kt < KT; kt++) {
        if (kt + 1 < KT) {
            loadA(buf ^ 1, (kt + 1) * BK);
            loadB(buf ^ 1, (kt + 1) * BK);
            cp_commit();
            asm volatile("cp.async.wait_group 1;\n");
        } else {
            asm volatile("cp.async.wait_group 0;\n");
        }
        __syncthreads();

        const float* A = sA[buf];
        const float* B = sB[buf];
        #pragma unroll
        for (int ks = 0; ks < 2; ks++) {
            const int k0s = ks * 8;
            uint32_t af[2][4], bf[4][2];
            #pragma unroll
            for (int mi = 0; mi < 2; mi++) {
                int r = mW + mi * 16;
                af[mi][0] = f2tf32(A[(r + g    ) * AS + k0s + t    ]);
                af[mi][1] = f2tf32(A[(r + g + 8) * AS + k0s + t    ]);
                af[mi][2] = f2tf32(A[(r + g    ) * AS + k0s + t + 4]);
                af[mi][3] = f2tf32(A[(r + g + 8) * AS + k0s + t + 4]);
            }
            #pragma unroll
            for (int ni = 0; ni < 4; ni++) {
                int cc = nW + ni * 8 + g;
                bf[ni][0] = f2tf32(B[(k0s + t    ) * BS + cc]);
                bf[ni][1] = f2tf32(B[(k0s + t + 4) * BS + cc]);
            }
            #pragma unroll
            for (int mi = 0; mi < 2; mi++)
                #pragma unroll
                for (int ni = 0; ni < 4; ni++)
                    mma_tf32(acc[mi][ni], af[mi], bf[ni]);
        }
        __syncthreads();
        buf ^= 1;
    }

    // epilogue: atomic accumulate split-K partials into g_xt
    #pragma unroll
    for (int mi = 0; mi < 2; mi++) {
        #pragma unroll
        for (int ni = 0; ni < 4; ni++) {
            int col = nW + ni * 8 + t * 2;
            int r0 = m0 + mW + mi * 16 + g;
            atomicAdd(&g_xt[(size_t)r0 * CODEN + col    ], acc[mi][ni][0]);
            atomicAdd(&g_xt[(size_t)r0 * CODEN + col + 1], acc[mi][ni][1]);
            atomicAdd(&g_xt[(size_t)(r0 + 8) * CODEN + col    ], acc[mi][ni][2]);
            atomicAdd(&g_xt[(size_t)(r0 + 8) * CODEN + col + 1], acc[mi][ni][3]);
        }
    }
}

// ---------------- hypergraph kernels ----------------
__global__ void zero_kernel(float* __restrict__ hid_raw) {
    int idx = blockIdx.x * blockDim.x + threadIdx.x;
    if (idx < NN * CODEN) {
        g_xt[idx] = 0.f;
        g_m[idx]  = 0.f;
        hid_raw[idx] = 0.f;
    }
    if (idx < NN) {
        g_Dcnt[idx] = 0.f;
        g_Bcnt[idx] = 0.f;
    }
}

__global__ void degree_kernel(const int* __restrict__ node, const int* __restrict__ edge) {
    int i = blockIdx.x * blockDim.x + threadIdx.x;
    if (i < EE) {
        atomicAdd(&g_Dcnt[node[i]], 1.f);
        atomicAdd(&g_Bcnt[edge[i]], 1.f);
    }
}

// m[e] += xt[node]   (per incidence entry; 16 threads per entry, float4 reads)
__global__ void scatter1_kernel(const int* __restrict__ node, const int* __restrict__ edge) {
    int idx = blockIdx.x * blockDim.x + threadIdx.x;
    if (idx >= EE * 16) return;
    int i  = idx >> 4;
    int c4 = idx & 15;
    int n = node[i];
    int e = edge[i];
    float4 v = reinterpret_cast<const float4*>(g_xt)[n * 16 + c4];
    float* dst = &g_m[e * CODEN + c4 * 4];
    atomicAdd(dst + 0, v.x);
    atomicAdd(dst + 1, v.y);
    atomicAdd(dst + 2, v.z);
    atomicAdd(dst + 3, v.w);
}

// hid_raw[n] += (m[e] * Binv[e])   (Binv folded in at gather, numerically identical)
__global__ void scatter2_kernel(const int* __restrict__ node, const int* __restrict__ edge,
                                float* __restrict__ hid_raw) {
    int idx = blockIdx.x * blockDim.x + threadIdx.x;
    if (idx >= EE * 16) return;
    int i  = idx >> 4;
    int c4 = idx & 15;
    int n = node[i];
    int e = edge[i];
    float bc = g_Bcnt[e];
    float binv = bc > 0.f ? 1.0f / bc : 0.f;
    float4 v = reinterpret_cast<const float4*>(g_m)[e * 16 + c4];
    float* dst = &hid_raw[n * CODEN + c4 * 4];
    atomicAdd(dst + 0, v.x * binv);
    atomicAdd(dst + 1, v.y * binv);
    atomicAdd(dst + 2, v.z * binv);
    atomicAdd(dst + 3, v.w * binv);
}

__global__ void finalize_kernel(float* __restrict__ hid, float* __restrict__ code,
                                const float* __restrict__ bias) {
    int idx = blockIdx.x * blockDim.x + threadIdx.x;
    if (idx >= NN * CODEN) return;
    int row = idx >> 6;
    int col = idx & 63;
    float d = g_Dcnt[row];
    float dinv = d > 0.f ? 1.0f / d : 0.f;
    float v = hid[idx] * dinv + bias[col];
    hid[idx]  = v;
    code[idx] = tanhf(v);
}

// ---------------- launch ----------------
extern "C" void kernel_launch(void* const* d_in, const int* in_sizes, int n_in,
                              void* d_out, int out_size) {
    const float* x     = (const float*)d_in[0];   // [8192, 1386]
    const float* W1    = (const float*)d_in[1];   // [1386, 4096]
    const float* b1    = (const float*)d_in[2];   // [4096]
    const float* theta = (const float*)d_in[3];   // [4096, 64]
    const float* bias  = (const float*)d_in[4];   // [64]
    const int*   hidx  = (const int*)d_in[5];     // [2, 262144]
    const int* node = hidx;
    const int* edge = hidx + EE;

    float* out  = (float*)d_out;
    float* feat = out;                                   // [8192, 4096]
    float* hid  = out + (size_t)NN * HIDN;               // [8192, 64]
    float* code = hid + (size_t)NN * CODEN;              // [8192, 64]

    zero_kernel<<<(NN * CODEN + 255) / 256, 256>>>(hid);
    gemm1_kernel<<<dim3(HIDN / 128, NN / 128), 256>>>(x, W1, b1, feat);
    degree_kernel<<<(EE + 255) / 256, 256>>>(node, edge);
    gemm2_kernel<<<dim3(4, NN / 128), 256>>>(feat, theta);
    scatter1_kernel<<<(EE * 16) / 256, 256>>>(node, edge);
    scatter2_kernel<<<(EE * 16) / 256, 256>>>(node, edge, hid);
    finalize_kernel<<<(NN * CODEN + 255) / 256, 256>>>(hid, code, bias);
}

// round 3
// speedup vs baseline: 1.6922x; 1.6922x over previous
#include <cuda_runtime.h>
#include <cuda_fp16.h>
#include <cstdint>
#include <cstddef>

#define NN    8192
#define EE    262144
#define FEATN 1386
#define HIDN  4096
#define CODEN 64
#define KP    1408       // FEATN padded to 32*44
#define KCH   44         // gemm1 K chunks of 32

// ---------------- scratch (no allocation allowed) ----------------
__device__ __half g_Xh[NN * KP];         // fp16-rounded, padded X      (23 MB)
__device__ __half g_Wth[HIDN * KP];      // fp16 W1^T [N][K], padded    (11.5 MB)
__device__ __half g_thT[CODEN * HIDN];   // fp16 theta^T [64][4096]     (0.5 MB)
__device__ __half g_feat_h[NN * HIDN];   // fp16 copy of feat           (67 MB)
__device__ float  g_xt[NN * CODEN];      // xt = feat @ theta           (2 MB)
__device__ float  g_m[NN * CODEN];       // per-hyperedge aggregate     (2 MB)
__device__ int    g_BcntI[NN];           // hyperedge degree (int)
__device__ int    g_DcntI[NN];           // node degree (int)
__device__ int    g_Boff[NN + 1];        // CSR offsets (edge -> entries)
__device__ int    g_Doff[NN + 1];        // CSR offsets (node -> entries)
__device__ int    g_Bcur[NN];
__device__ int    g_Dcur[NN];
__device__ int    g_Blist[EE];           // node ids grouped by edge
__device__ int    g_Dlist[EE];           // edge ids grouped by node

// ---------------- helpers ----------------
__device__ __forceinline__ void cp_async16(uint32_t smem, const void* gmem) {
    asm volatile("cp.async.cg.shared.global [%0], [%1], 16;\n" :: "r"(smem), "l"(gmem));
}
__device__ __forceinline__ void cp_commit() { asm volatile("cp.async.commit_group;\n"); }

__device__ __forceinline__ void mma_f16(float c[4], const uint32_t a[4], const uint32_t b[2]) {
    asm volatile(
        "mma.sync.aligned.m16n8k16.row.col.f32.f16.f16.f32 "
        "{%0,%1,%2,%3}, {%4,%5,%6,%7}, {%8,%9}, {%0,%1,%2,%3};\n"
        : "+f"(c[0]), "+f"(c[1]), "+f"(c[2]), "+f"(c[3])
        : "r"(a[0]), "r"(a[1]), "r"(a[2]), "r"(a[3]), "r"(b[0]), "r"(b[1]));
}

// ---------------- zero scratch ----------------
__global__ void zero_kernel() {
    int idx = blockIdx.x * blockDim.x + threadIdx.x;
    if (idx < NN * CODEN) g_xt[idx] = 0.f;
    if (idx < NN) { g_BcntI[idx] = 0; g_DcntI[idx] = 0; }
}

// ---------------- prepass: round X -> half, pad K ----------------
__global__ void round_x_h(const float* __restrict__ x) {
    int idx = blockIdx.x * 256 + threadIdx.x;           // one half2 per thread
    if (idx >= NN * (KP / 2)) return;
    int row = idx / (KP / 2);
    int p   = idx - row * (KP / 2);
    int col = p * 2;
    __half2 h = __float2half2_rn(0.f);
    if (col < FEATN) {
        float2 v = *reinterpret_cast<const float2*>(x + (size_t)row * FEATN + col);
        h = __floats2half2_rn(v.x, v.y);
    }
    *reinterpret_cast<__half2*>(&g_Xh[(size_t)row * KP + col]) = h;
}

// ---------------- prepass: W1 -> half, transpose to [N][K], pad ----------------
__global__ void round_wt_h(const float* __restrict__ W) {
    __shared__ float ts[32][33];
    int kb = blockIdx.x * 32, nb = blockIdx.y * 32;
    int tx = threadIdx.x, ty = threadIdx.y;   // (32, 8)
    #pragma unroll
    for (int i = 0; i < 4; i++) {
        int k = kb + ty + i * 8;
        float v = 0.f;
        if (k < FEATN) v = W[(size_t)k * HIDN + nb + tx];
        ts[ty + i * 8][tx] = v;
    }
    __syncthreads();
    #pragma unroll
    for (int i = 0; i < 4; i++)
        g_Wth[(size_t)(nb + ty + i * 8) * KP + kb + tx] = __float2half_rn(ts[tx][ty + i * 8]);
}

// ---------------- prepass: theta -> half, transpose to [64][4096] ----------------
__global__ void round_th_h(const float* __restrict__ th) {
    __shared__ float ts[32][33];
    int kb = blockIdx.x * 32, nb = blockIdx.y * 32;
    int tx = threadIdx.x, ty = threadIdx.y;   // (32, 8)
    #pragma unroll
    for (int i = 0; i < 4; i++)
        ts[ty + i * 8][tx] = th[(size_t)(kb + ty + i * 8) * CODEN + nb + tx];
    __syncthreads();
    #pragma unroll
    for (int i = 0; i < 4; i++)
        g_thT[(size_t)(nb + ty + i * 8) * HIDN + kb + tx] = __float2half_rn(ts[tx][ty + i * 8]);
}

// ---------------- GEMM1: feat = relu(Xh @ Wth^T + b1), fp16 mma ----------------
// BM=128, BN=128, BK=32 halves, 256 threads, 2 CTAs/SM.
__global__ __launch_bounds__(256, 2)
void gemm1_h(const float* __restrict__ bias1, float* __restrict__ feat) {
    constexpr int AS = 40;   // smem row stride in halves (80 B)
    __shared__ __half sA[2][128 * AS];
    __shared__ __half sB[2][128 * AS];

    const int tid = threadIdx.x;
    const int m0 = blockIdx.y * 128;
    const int n0 = blockIdx.x * 128;

    const __half* Abase = g_Xh + (size_t)m0 * KP;
    const __half* Bbase = g_Wth + (size_t)n0 * KP;

    auto loadA = [&](int buf, int kc) {
        #pragma unroll
        for (int i = 0; i < 2; i++) {
            int c = tid + i * 256;            // 0..511
            int row = c >> 2, ch = c & 3;
            const __half* src = Abase + (size_t)row * KP + kc * 32 + ch * 8;
            cp_async16((uint32_t)__cvta_generic_to_shared(&sA[buf][row * AS + ch * 8]), src);
        }
    };
    auto loadB = [&](int buf, int kc) {
        #pragma unroll
        for (int i = 0; i < 2; i++) {
            int c = tid + i * 256;
            int row = c >> 2, ch = c & 3;
            const __half* src = Bbase + (size_t)row * KP + kc * 32 + ch * 8;
            cp_async16((uint32_t)__cvta_generic_to_shared(&sB[buf][row * AS + ch * 8]), src);
        }
    };

    float acc[4][4][4];
    #pragma unroll
    for (int mi = 0; mi < 4; mi++)
        #pragma unroll
        for (int ni = 0; ni < 4; ni++)
            #pragma unroll
            for (int r = 0; r < 4; r++) acc[mi][ni][r] = 0.f;

    loadA(0, 0); loadB(0, 0); cp_commit();

    const int warp = tid >> 5, lane = tid & 31;
    const int wm = warp & 1, wn = warp >> 1;       // 2 x 4 warp grid
    const int mW = wm * 64, nW = wn * 32;          // warp tile 64 x 32
    const int g = lane >> 2, t = lane & 3;

    int buf = 0;
    for (int kt = 0; kt < KCH; kt++) {
        if (kt + 1 < KCH) {
            loadA(buf ^ 1, kt + 1);
            loadB(buf ^ 1, kt + 1);
            cp_commit();
            asm volatile("cp.async.wait_group 1;\n");
        } else {
            asm volatile("cp.async.wait_group 0;\n");
        }
        __syncthreads();

        const __half* A = sA[buf];
        const __half* B = sB[buf];
        #pragma unroll
        for (int ks = 0; ks < 2; ks++) {
            const int k0s = ks * 16;
            uint32_t af[4][4], bf[4][2];
            #pragma unroll
            for (int mi = 0; mi < 4; mi++) {
                int r = mW + mi * 16;
                af[mi][0] = *reinterpret_cast<const uint32_t*>(&A[(r + g    ) * AS + k0s + 2 * t    ]);
                af[mi][1] = *reinterpret_cast<const uint32_t*>(&A[(r + g + 8) * AS + k0s + 2 * t    ]);
                af[mi][2] = *reinterpret_cast<const uint32_t*>(&A[(r + g    ) * AS + k0s + 2 * t + 8]);
                af[mi][3] = *reinterpret_cast<const uint32_t*>(&A[(r + g + 8) * AS + k0s + 2 * t + 8]);
            }
            #pragma unroll
            for (int ni = 0; ni < 4; ni++) {
                int n = nW + ni * 8 + g;
                bf[ni][0] = *reinterpret_cast<const uint32_t*>(&B[n * AS + k0s + 2 * t    ]);
                bf[ni][1] = *reinterpret_cast<const uint32_t*>(&B[n * AS + k0s + 2 * t + 8]);
            }
            #pragma unroll
            for (int mi = 0; mi < 4; mi++)
                #pragma unroll
                for (int ni = 0; ni < 4; ni++)
                    mma_f16(acc[mi][ni], af[mi], bf[ni]);
        }
        __syncthreads();
        buf ^= 1;
    }

    // epilogue: +bias, relu, store fp32 feat + fp16 copy
    #pragma unroll
    for (int mi = 0; mi < 4; mi++) {
        #pragma unroll
        for (int ni = 0; ni < 4; ni++) {
            int col = n0 + nW + ni * 8 + t * 2;
            float bv0 = bias1[col], bv1 = bias1[col + 1];
            int r0 = m0 + mW + mi * 16 + g;
            float v0 = fmaxf(acc[mi][ni][0] + bv0, 0.f);
            float v1 = fmaxf(acc[mi][ni][1] + bv1, 0.f);
            *reinterpret_cast<float2*>(&feat[(size_t)r0 * HIDN + col]) = make_float2(v0, v1);
            *reinterpret_cast<__half2*>(&g_feat_h[(size_t)r0 * HIDN + col]) = __floats2half2_rn(v0, v1);
            float v2 = fmaxf(acc[mi][ni][2] + bv0, 0.f);
            float v3 = fmaxf(acc[mi][ni][3] + bv1, 0.f);
            *reinterpret_cast<float2*>(&feat[(size_t)(r0 + 8) * HIDN + col]) = make_float2(v2, v3);
            *reinterpret_cast<__half2*>(&g_feat_h[(size_t)(r0 + 8) * HIDN + col]) = __floats2half2_rn(v2, v3);
        }
    }
}

// ---------------- GEMM2: xt = feat_h @ thT^T, fp16 mma, split-K atomics ----------
// BM=128, BN=64, BK=32, split-K = 4 x 1024.
__global__ __launch_bounds__(256, 2)
void gemm2_h() {
    constexpr int AS = 40;
    __shared__ __half sA[2][128 * AS];
    __shared__ __half sB[2][64 * AS];

    const int tid = threadIdx.x;
    const int m0 = blockIdx.y * 128;
    const int kbase = blockIdx.x * 1024;
    const int KT = 1024 / 32;   // 32

    const __half* Abase = g_feat_h + (size_t)m0 * HIDN + kbase;

    auto loadA = [&](int buf, int kc) {
        #pragma unroll
        for (int i = 0; i < 2; i++) {
            int c = tid + i * 256;
            int row = c >> 2, ch = c & 3;
            const __half* src = Abase + (size_t)row * HIDN + kc * 32 + ch * 8;
            cp_async16((uint32_t)__cvta_generic_to_shared(&sA[buf][row * AS + ch * 8]), src);
        }
    };
    auto loadB = [&](int buf, int kc) {
        int row = tid >> 2, ch = tid & 3;     // 64 rows x 4 chunks
        const __half* src = g_thT + (size_t)row * HIDN + kbase + kc * 32 + ch * 8;
        cp_async16((uint32_t)__cvta_generic_to_shared(&sB[buf][row * AS + ch * 8]), src);
    };

    float acc[2][4][4];
    #pragma unroll
    for (int mi = 0; mi < 2; mi++)
        #pragma unroll
        for (int ni = 0; ni < 4; ni++)
            #pragma unroll
            for (int r = 0; r < 4; r++) acc[mi][ni][r] = 0.f;

    loadA(0, 0); loadB(0, 0); cp_commit();

    const int warp = tid >> 5, lane = tid & 31;
    const int wm = warp & 3, wn = warp >> 2;   // 4 x 2
    const int mW = wm * 32, nW = wn * 32;      // warp tile 32 x 32
    const int g = lane >> 2, t = lane & 3;

    int buf = 0;
    for (int kt = 0; kt < KT; kt++) {
        if (kt + 1 < KT) {
            loadA(buf ^ 1, kt + 1);
            loadB(buf ^ 1, kt + 1);
            cp_commit();
            asm volatile("cp.async.wait_group 1;\n");
        } else {
            asm volatile("cp.async.wait_group 0;\n");
        }
        __syncthreads();

        const __half* A = sA[buf];
        const __half* B = sB[buf];
        #pragma unroll
        for (int ks = 0; ks < 2; ks++) {
            const int k0s = ks * 16;
            uint32_t af[2][4], bf[4][2];
            #pragma unroll
            for (int mi = 0; mi < 2; mi++) {
                int r = mW + mi * 16;
                af[mi][0] = *reinterpret_cast<const uint32_t*>(&A[(r + g    ) * AS + k0s + 2 * t    ]);
                af[mi][1] = *reinterpret_cast<const uint32_t*>(&A[(r + g + 8) * AS + k0s + 2 * t    ]);
                af[mi][2] = *reinterpret_cast<const uint32_t*>(&A[(r + g    ) * AS + k0s + 2 * t + 8]);
                af[mi][3] = *reinterpret_cast<const uint32_t*>(&A[(r + g + 8) * AS + k0s + 2 * t + 8]);
            }
            #pragma unroll
            for (int ni = 0; ni < 4; ni++) {
                int n = nW + ni * 8 + g;
                bf[ni][0] = *reinterpret_cast<const uint32_t*>(&B[n * AS + k0s + 2 * t    ]);
                bf[ni][1] = *reinterpret_cast<const uint32_t*>(&B[n * AS + k0s + 2 * t + 8]);
            }
            #pragma unroll
            for (int mi = 0; mi < 2; mi++)
                #pragma unroll
                for (int ni = 0; ni < 4; ni++)
                    mma_f16(acc[mi][ni], af[mi], bf[ni]);
        }
        __syncthreads();
        buf ^= 1;
    }

    #pragma unroll
    for (int mi = 0; mi < 2; mi++) {
        #pragma unroll
        for (int ni = 0; ni < 4; ni++) {
            int col = nW + ni * 8 + t * 2;
            int r0 = m0 + mW + mi * 16 + g;
            atomicAdd(&g_xt[(size_t)r0 * CODEN + col    ], acc[mi][ni][0]);
            atomicAdd(&g_xt[(size_t)r0 * CODEN + col + 1], acc[mi][ni][1]);
            atomicAdd(&g_xt[(size_t)(r0 + 8) * CODEN + col    ], acc[mi][ni][2]);
            atomicAdd(&g_xt[(size_t)(r0 + 8) * CODEN + col + 1], acc[mi][ni][3]);
        }
    }
}

// ---------------- CSR build ----------------
__global__ void degree_kernel(const int* __restrict__ node, const int* __restrict__ edge) {
    int i = blockIdx.x * blockDim.x + threadIdx.x;
    if (i < EE) {
        atomicAdd(&g_DcntI[node[i]], 1);
        atomicAdd(&g_BcntI[edge[i]], 1);
    }
}

__global__ void scan_kernel() {   // blockIdx.x: 0 -> B (edge), 1 -> D (node)
    const int* cnt = blockIdx.x ? g_DcntI : g_BcntI;
    int* off = blockIdx.x ? g_Doff : g_Boff;
    int* cur = blockIdx.x ? g_Dcur : g_Bcur;
    __shared__ int part[1024];
    int t = threadIdx.x;
    int base = t * 8;
    int loc[8];
    int s = 0;
    #pragma unroll
    for (int i = 0; i < 8; i++) { loc[i] = s; s += cnt[base + i]; }
    part[t] = s;
    __syncthreads();
    for (int ofs = 1; ofs < 1024; ofs <<= 1) {
        int v = (t >= ofs) ? part[t - ofs] : 0;
        __syncthreads();
        part[t] += v;
        __syncthreads();
    }
    int prev = (t == 0) ? 0 : part[t - 1];
    #pragma unroll
    for (int i = 0; i < 8; i++) { off[base + i] = prev + loc[i]; cur[base + i] = prev + loc[i]; }
    if (t == 1023) off[NN] = part[1023];
}

__global__ void fill_kernel(const int* __restrict__ node, const int* __restrict__ edge) {
    int i = blockIdx.x * blockDim.x + threadIdx.x;
    if (i >= EE) return;
    int n = node[i], e = edge[i];
    int p = atomicAdd(&g_Bcur[e], 1);
    g_Blist[p] = n;
    int q = atomicAdd(&g_Dcur[n], 1);
    g_Dlist[q] = e;
}

// ---------------- gathers (dense per-segment sums, no float atomics) ----------
__global__ void gather1_kernel() {    // m[e] = (sum_{n in list(e)} xt[n]) * Binv
    int e = blockIdx.x * 4 + (threadIdx.x >> 6);
    int f = threadIdx.x & 63;
    int s = g_Boff[e], t = g_Boff[e + 1];
    float acc = 0.f;
    int j = s;
    for (; j + 1 < t; j += 2) {
        int n0 = g_Blist[j], n1 = g_Blist[j + 1];
        acc += g_xt[n0 * CODEN + f] + g_xt[n1 * CODEN + f];
    }
    if (j < t) acc += g_xt[g_Blist[j] * CODEN + f];
    float binv = (t > s) ? 1.f / (float)(t - s) : 0.f;
    g_m[e * CODEN + f] = acc * binv;
}

__global__ void gather2_kernel(float* __restrict__ hid, float* __restrict__ code,
                               const float* __restrict__ bias) {
    int n = blockIdx.x * 4 + (threadIdx.x >> 6);
    int f = threadIdx.x & 63;
    int s = g_Doff[n], t = g_Doff[n + 1];
    float acc = 0.f;
    int j = s;
    for (; j + 1 < t; j += 2) {
        int e0 = g_Dlist[j], e1 = g_Dlist[j + 1];
        acc += g_m[e0 * CODEN + f] + g_m[e1 * CODEN + f];
    }
    if (j < t) acc += g_m[g_Dlist[j] * CODEN + f];
    float dinv = (t > s) ? 1.f / (float)(t - s) : 0.f;
    float v = acc * dinv + bias[f];
    hid[n * CODEN + f] = v;
    code[n * CODEN + f] = tanhf(v);
}

// ---------------- launch ----------------
extern "C" void kernel_launch(void* const* d_in, const int* in_sizes, int n_in,
                              void* d_out, int out_size) {
    const float* x     = (const float*)d_in[0];   // [8192, 1386]
    const float* W1    = (const float*)d_in[1];   // [1386, 4096]
    const float* b1    = (const float*)d_in[2];   // [4096]
    const float* theta = (const float*)d_in[3];   // [4096, 64]
    const float* bias  = (const float*)d_in[4];   // [64]
    const int*   hidx  = (const int*)d_in[5];     // [2, 262144]
    const int* node = hidx;
    const int* edge = hidx + EE;

    float* out  = (float*)d_out;
    float* feat = out;                               // [8192, 4096]
    float* hid  = out + (size_t)NN * HIDN;           // [8192, 64]
    float* code = hid + (size_t)NN * CODEN;          // [8192, 64]

    zero_kernel<<<(NN * CODEN + 255) / 256, 256>>>();
    round_x_h<<<(NN * (KP / 2) + 255) / 256, 256>>>(x);
    round_wt_h<<<dim3(KP / 32, HIDN / 32), dim3(32, 8)>>>(W1);
    round_th_h<<<dim3(HIDN / 32, CODEN / 32), dim3(32, 8)>>>(theta);
    degree_kernel<<<(EE + 255) / 256, 256>>>(node, edge);
    scan_kernel<<<2, 1024>>>();
    fill_kernel<<<(EE + 255) / 256, 256>>>(node, edge);
    gemm1_h<<<dim3(HIDN / 128, NN / 128), 256>>>(b1, feat);
    gemm2_h<<<dim3(4, NN / 128), 256>>>();
    gather1_kernel<<<NN / 4, 256>>>();
    gather2_kernel<<<NN / 4, 256>>>(hid, code, bias);
}

// round 5
// speedup vs baseline: 1.8326x; 1.0829x over previous
#include <cuda_runtime.h>
#include <cuda_fp16.h>
#include <cstdint>
#include <cstddef>

#define NN    8192
#define EE    262144
#define FEATN 1386
#define HIDN  4096
#define CODEN 64
#define KP    1408       // FEATN padded to 32*44
#define KCH   44         // gemm1 K chunks of 32

// ---------------- scratch (no allocation allowed) ----------------
__device__ __half g_Xh[NN * KP];         // fp16-rounded, padded X      (23 MB)
__device__ __half g_Wth[HIDN * KP];      // fp16 W1^T [N][K], padded    (11.5 MB)
__device__ __half g_thT[CODEN * HIDN];   // fp16 theta^T [64][4096]     (0.5 MB)
__device__ __half g_feat_h[NN * HIDN];   // fp16 copy of feat           (67 MB)
__device__ float  g_xt[NN * CODEN];      // xt = feat @ theta           (2 MB)
__device__ float  g_m[NN * CODEN];       // per-hyperedge aggregate     (2 MB)
__device__ int    g_BcntI[NN];
__device__ int    g_DcntI[NN];
__device__ int    g_Boff[NN + 1];
__device__ int    g_Doff[NN + 1];
__device__ int    g_Bcur[NN];
__device__ int    g_Dcur[NN];
__device__ int    g_Blist[EE];
__device__ int    g_Dlist[EE];

// ---------------- helpers ----------------
__device__ __forceinline__ void cp_async16(uint32_t smem, const void* gmem) {
    asm volatile("cp.async.cg.shared.global [%0], [%1], 16;\n" :: "r"(smem), "l"(gmem));
}
__device__ __forceinline__ void cp_commit() { asm volatile("cp.async.commit_group;\n"); }

__device__ __forceinline__ void mma_f16(float c[4], const uint32_t a[4], const uint32_t b[2]) {
    asm volatile(
        "mma.sync.aligned.m16n8k16.row.col.f32.f16.f16.f32 "
        "{%0,%1,%2,%3}, {%4,%5,%6,%7}, {%8,%9}, {%0,%1,%2,%3};\n"
        : "+f"(c[0]), "+f"(c[1]), "+f"(c[2]), "+f"(c[3])
        : "r"(a[0]), "r"(a[1]), "r"(a[2]), "r"(a[3]), "r"(b[0]), "r"(b[1]));
}

__device__ __forceinline__ void ldsm_x4(uint32_t r[4], uint32_t addr) {
    asm volatile("ldmatrix.sync.aligned.m8n8.x4.shared.b16 {%0,%1,%2,%3}, [%4];"
                 : "=r"(r[0]), "=r"(r[1]), "=r"(r[2]), "=r"(r[3]) : "r"(addr));
}

// ---------------- zero scratch ----------------
__global__ void zero_kernel() {
    int idx = blockIdx.x * blockDim.x + threadIdx.x;
    if (idx < NN * CODEN) g_xt[idx] = 0.f;
    if (idx < NN) { g_BcntI[idx] = 0; g_DcntI[idx] = 0; }
}

// ---------------- prepass: round X -> half, pad K ----------------
__global__ void round_x_h(const float* __restrict__ x) {
    int idx = blockIdx.x * 256 + threadIdx.x;
    if (idx >= NN * (KP / 2)) return;
    int row = idx / (KP / 2);
    int p   = idx - row * (KP / 2);
    int col = p * 2;
    __half2 h = __float2half2_rn(0.f);
    if (col < FEATN) {
        float2 v = *reinterpret_cast<const float2*>(x + (size_t)row * FEATN + col);
        h = __floats2half2_rn(v.x, v.y);
    }
    *reinterpret_cast<__half2*>(&g_Xh[(size_t)row * KP + col]) = h;
}

// ---------------- prepass: W1 -> half, transpose to [N][K], pad ----------------
__global__ void round_wt_h(const float* __restrict__ W) {
    __shared__ float ts[32][33];
    int kb = blockIdx.x * 32, nb = blockIdx.y * 32;
    int tx = threadIdx.x, ty = threadIdx.y;
    #pragma unroll
    for (int i = 0; i < 4; i++) {
        int k = kb + ty + i * 8;
        float v = 0.f;
        if (k < FEATN) v = W[(size_t)k * HIDN + nb + tx];
        ts[ty + i * 8][tx] = v;
    }
    __syncthreads();
    #pragma unroll
    for (int i = 0; i < 4; i++)
        g_Wth[(size_t)(nb + ty + i * 8) * KP + kb + tx] = __float2half_rn(ts[tx][ty + i * 8]);
}

// ---------------- prepass: theta -> half, transpose to [64][4096] ----------------
__global__ void round_th_h(const float* __restrict__ th) {
    __shared__ float ts[32][33];
    int kb = blockIdx.x * 32, nb = blockIdx.y * 32;
    int tx = threadIdx.x, ty = threadIdx.y;
    #pragma unroll
    for (int i = 0; i < 4; i++)
        ts[ty + i * 8][tx] = th[(size_t)(kb + ty + i * 8) * CODEN + nb + tx];
    __syncthreads();
    #pragma unroll
    for (int i = 0; i < 4; i++)
        g_thT[(size_t)(nb + ty + i * 8) * HIDN + kb + tx] = __float2half_rn(ts[tx][ty + i * 8]);
}

// ---------------- GEMM1: feat = relu(Xh @ Wth^T + b1), fp16 mma + ldmatrix ----
// BM=128, BN=128, BK=32 halves, 256 threads, 2 CTAs/SM.
__global__ __launch_bounds__(256, 2)
void gemm1_h(const float* __restrict__ bias1, float* __restrict__ feat) {
    constexpr int AS = 40;   // smem row stride in halves (80 B, 16B-aligned, 5 chunks)
    __shared__ __half sA[2][128 * AS];
    __shared__ __half sB[2][128 * AS];

    const int tid = threadIdx.x;
    const int m0 = blockIdx.y * 128;
    const int n0 = blockIdx.x * 128;

    const __half* Abase = g_Xh + (size_t)m0 * KP;
    const __half* Bbase = g_Wth + (size_t)n0 * KP;

    auto loadA = [&](int buf, int kc) {
        #pragma unroll
        for (int i = 0; i < 2; i++) {
            int c = tid + i * 256;
            int row = c >> 2, ch = c & 3;
            const __half* src = Abase + (size_t)row * KP + kc * 32 + ch * 8;
            cp_async16((uint32_t)__cvta_generic_to_shared(&sA[buf][row * AS + ch * 8]), src);
        }
    };
    auto loadB = [&](int buf, int kc) {
        #pragma unroll
        for (int i = 0; i < 2; i++) {
            int c = tid + i * 256;
            int row = c >> 2, ch = c & 3;
            const __half* src = Bbase + (size_t)row * KP + kc * 32 + ch * 8;
            cp_async16((uint32_t)__cvta_generic_to_shared(&sB[buf][row * AS + ch * 8]), src);
        }
    };

    float acc[4][4][4];
    #pragma unroll
    for (int mi = 0; mi < 4; mi++)
        #pragma unroll
        for (int ni = 0; ni < 4; ni++)
            #pragma unroll
            for (int r = 0; r < 4; r++) acc[mi][ni][r] = 0.f;

    loadA(0, 0); loadB(0, 0); cp_commit();

    const int warp = tid >> 5, lane = tid & 31;
    const int wm = warp & 1, wn = warp >> 1;       // 2 x 4 warp grid
    const int mW = wm * 64, nW = wn * 32;          // warp tile 64 x 32
    const int g = lane >> 2, t = lane & 3;

    // ldmatrix lane address components (element offsets within tile)
    const int aRow = mW + (lane & 15);                       // + mi*16
    const int aK   = (lane >> 4) * 8;                        // + k0s
    const int bRow = nW + ((lane >> 4) << 3) + (lane & 7);   // covers 16 n
    const int bK   = ((lane >> 3) & 1) * 8;                  // + k0s

    int buf = 0;
    for (int kt = 0; kt < KCH; kt++) {
        if (kt + 1 < KCH) {
            loadA(buf ^ 1, kt + 1);
            loadB(buf ^ 1, kt + 1);
            cp_commit();
            asm volatile("cp.async.wait_group 1;\n");
        } else {
            asm volatile("cp.async.wait_group 0;\n");
        }
        __syncthreads();

        const __half* A = sA[buf];
        const __half* B = sB[buf];
        uint32_t aAddr0 = (uint32_t)__cvta_generic_to_shared(&A[aRow * AS + aK]);
        uint32_t bAddr0 = (uint32_t)__cvta_generic_to_shared(&B[bRow * AS + bK]);
        #pragma unroll
        for (int ks = 0; ks < 2; ks++) {
            const uint32_t kOff = ks * 16 * 2;   // bytes
            uint32_t af[4][4], bf[4][2];
            #pragma unroll
            for (int mi = 0; mi < 4; mi++)
                ldsm_x4(af[mi], aAddr0 + kOff + mi * 16 * AS * 2);
            #pragma unroll
            for (int p = 0; p < 2; p++) {
                uint32_t r[4];
                ldsm_x4(r, bAddr0 + kOff + p * 16 * AS * 2);
                bf[2 * p][0] = r[0]; bf[2 * p][1] = r[1];
                bf[2 * p + 1][0] = r[2]; bf[2 * p + 1][1] = r[3];
            }
            #pragma unroll
            for (int mi = 0; mi < 4; mi++)
                #pragma unroll
                for (int ni = 0; ni < 4; ni++)
                    mma_f16(acc[mi][ni], af[mi], bf[ni]);
        }
        __syncthreads();
        buf ^= 1;
    }

    // epilogue: +bias, relu, store fp32 feat + fp16 copy
    #pragma unroll
    for (int mi = 0; mi < 4; mi++) {
        #pragma unroll
        for (int ni = 0; ni < 4; ni++) {
            int col = n0 + nW + ni * 8 + t * 2;
            float bv0 = bias1[col], bv1 = bias1[col + 1];
            int r0 = m0 + mW + mi * 16 + g;
            float v0 = fmaxf(acc[mi][ni][0] + bv0, 0.f);
            float v1 = fmaxf(acc[mi][ni][1] + bv1, 0.f);
            *reinterpret_cast<float2*>(&feat[(size_t)r0 * HIDN + col]) = make_float2(v0, v1);
            *reinterpret_cast<__half2*>(&g_feat_h[(size_t)r0 * HIDN + col]) = __floats2half2_rn(v0, v1);
            float v2 = fmaxf(acc[mi][ni][2] + bv0, 0.f);
            float v3 = fmaxf(acc[mi][ni][3] + bv1, 0.f);
            *reinterpret_cast<float2*>(&feat[(size_t)(r0 + 8) * HIDN + col]) = make_float2(v2, v3);
            *reinterpret_cast<__half2*>(&g_feat_h[(size_t)(r0 + 8) * HIDN + col]) = __floats2half2_rn(v2, v3);
        }
    }
}

// ---------------- GEMM2: xt = feat_h @ thT^T, fp16 mma + ldmatrix ----------
// BM=128, BN=64, BK=32, split-K = 4 x 1024.
__global__ __launch_bounds__(256, 2)
void gemm2_h() {
    constexpr int AS = 40;
    __shared__ __half sA[2][128 * AS];
    __shared__ __half sB[2][64 * AS];

    const int tid = threadIdx.x;
    const int m0 = blockIdx.y * 128;
    const int kbase = blockIdx.x * 1024;
    const int KT = 1024 / 32;

    const __half* Abase = g_feat_h + (size_t)m0 * HIDN + kbase;

    auto loadA = [&](int buf, int kc) {
        #pragma unroll
        for (int i = 0; i < 2; i++) {
            int c = tid + i * 256;
            int row = c >> 2, ch = c & 3;
            const __half* src = Abase + (size_t)row * HIDN + kc * 32 + ch * 8;
            cp_async16((uint32_t)__cvta_generic_to_shared(&sA[buf][row * AS + ch * 8]), src);
        }
    };
    auto loadB = [&](int buf, int kc) {
        int row = tid >> 2, ch = tid & 3;
        const __half* src = g_thT + (size_t)row * HIDN + kbase + kc * 32 + ch * 8;
        cp_async16((uint32_t)__cvta_generic_to_shared(&sB[buf][row * AS + ch * 8]), src);
    };

    float acc[2][4][4];
    #pragma unroll
    for (int mi = 0; mi < 2; mi++)
        #pragma unroll
        for (int ni = 0; ni < 4; ni++)
            #pragma unroll
            for (int r = 0; r < 4; r++) acc[mi][ni][r] = 0.f;

    loadA(0, 0); loadB(0, 0); cp_commit();

    const int warp = tid >> 5, lane = tid & 31;
    const int wm = warp & 3, wn = warp >> 2;
    const int mW = wm * 32, nW = wn * 32;
    const int g = lane >> 2, t = lane & 3;

    const int aRow = mW + (lane & 15);
    const int aK   = (lane >> 4) * 8;
    const int bRow = nW + ((lane >> 4) << 3) + (lane & 7);
    const int bK   = ((lane >> 3) & 1) * 8;

    int buf = 0;
    for (int kt = 0; kt < KT; kt++) {
        if (kt + 1 < KT) {
            loadA(buf ^ 1, kt + 1);
            loadB(buf ^ 1, kt + 1);
            cp_commit();
            asm volatile("cp.async.wait_group 1;\n");
        } else {
            asm volatile("cp.async.wait_group 0;\n");
        }
        __syncthreads();

        const __half* A = sA[buf];
        const __half* B = sB[buf];
        uint32_t aAddr0 = (uint32_t)__cvta_generic_to_shared(&A[aRow * AS + aK]);
        uint32_t bAddr0 = (uint32_t)__cvta_generic_to_shared(&B[bRow * AS + bK]);
        #pragma unroll
        for (int ks = 0; ks < 2; ks++) {
            const uint32_t kOff = ks * 16 * 2;
            uint32_t af[2][4], bf[4][2];
            #pragma unroll
            for (int mi = 0; mi < 2; mi++)
                ldsm_x4(af[mi], aAddr0 + kOff + mi * 16 * AS * 2);
            #pragma unroll
            for (int p = 0; p < 2; p++) {
                uint32_t r[4];
                ldsm_x4(r, bAddr0 + kOff + p * 16 * AS * 2);
                bf[2 * p][0] = r[0]; bf[2 * p][1] = r[1];
                bf[2 * p + 1][0] = r[2]; bf[2 * p + 1][1] = r[3];
            }
            #pragma unroll
            for (int mi = 0; mi < 2; mi++)
                #pragma unroll
                for (int ni = 0; ni < 4; ni++)
                    mma_f16(acc[mi][ni], af[mi], bf[ni]);
        }
        __syncthreads();
        buf ^= 1;
    }

    #pragma unroll
    for (int mi = 0; mi < 2; mi++) {
        #pragma unroll
        for (int ni = 0; ni < 4; ni++) {
            int col = nW + ni * 8 + t * 2;
            int r0 = m0 + mW + mi * 16 + g;
            atomicAdd(&g_xt[(size_t)r0 * CODEN + col    ], acc[mi][ni][0]);
            atomicAdd(&g_xt[(size_t)r0 * CODEN + col + 1], acc[mi][ni][1]);
            atomicAdd(&g_xt[(size_t)(r0 + 8) * CODEN + col    ], acc[mi][ni][2]);
            atomicAdd(&g_xt[(size_t)(r0 + 8) * CODEN + col + 1], acc[mi][ni][3]);
        }
    }
}

// ---------------- CSR build ----------------
__global__ void degree_kernel(const int* __restrict__ node, const int* __restrict__ edge) {
    int i = blockIdx.x * blockDim.x + threadIdx.x;
    if (i < EE) {
        atomicAdd(&g_DcntI[node[i]], 1);
        atomicAdd(&g_BcntI[edge[i]], 1);
    }
}

__global__ void scan_kernel() {
    const int* cnt = blockIdx.x ? g_DcntI : g_BcntI;
    int* off = blockIdx.x ? g_Doff : g_Boff;
    int* cur = blockIdx.x ? g_Dcur : g_Bcur;
    __shared__ int part[1024];
    int t = threadIdx.x;
    int base = t * 8;
    int loc[8];
    int s = 0;
    #pragma unroll
    for (int i = 0; i < 8; i++) { loc[i] = s; s += cnt[base + i]; }
    part[t] = s;
    __syncthreads();
    for (int ofs = 1; ofs < 1024; ofs <<= 1) {
        int v = (t >= ofs) ? part[t - ofs] : 0;
        __syncthreads();
        part[t] += v;
        __syncthreads();
    }
    int prev = (t == 0) ? 0 : part[t - 1];
    #pragma unroll
    for (int i = 0; i < 8; i++) { off[base + i] = prev + loc[i]; cur[base + i] = prev + loc[i]; }
    if (t == 1023) off[NN] = part[1023];
}

__global__ void fill_kernel(const int* __restrict__ node, const int* __restrict__ edge) {
    int i = blockIdx.x * blockDim.x + threadIdx.x;
    if (i >= EE) return;
    int n = node[i], e = edge[i];
    int p = atomicAdd(&g_Bcur[e], 1);
    g_Blist[p] = n;
    int q = atomicAdd(&g_Dcur[n], 1);
    g_Dlist[q] = e;
}

// ---------------- gathers ----------------
__global__ void gather1_kernel() {
    int e = blockIdx.x * 4 + (threadIdx.x >> 6);
    int f = threadIdx.x & 63;
    int s = g_Boff[e], t = g_Boff[e + 1];
    float acc = 0.f;
    int j = s;
    for (; j + 1 < t; j += 2) {
        int n0 = g_Blist[j], n1 = g_Blist[j + 1];
        acc += g_xt[n0 * CODEN + f] + g_xt[n1 * CODEN + f];
    }
    if (j < t) acc += g_xt[g_Blist[j] * CODEN + f];
    float binv = (t > s) ? 1.f / (float)(t - s) : 0.f;
    g_m[e * CODEN + f] = acc * binv;
}

__global__ void gather2_kernel(float* __restrict__ hid, float* __restrict__ code,
                               const float* __restrict__ bias) {
    int n = blockIdx.x * 4 + (threadIdx.x >> 6);
    int f = threadIdx.x & 63;
    int s = g_Doff[n], t = g_Doff[n + 1];
    float acc = 0.f;
    int j = s;
    for (; j + 1 < t; j += 2) {
        int e0 = g_Dlist[j], e1 = g_Dlist[j + 1];
        acc += g_m[e0 * CODEN + f] + g_m[e1 * CODEN + f];
    }
    if (j < t) acc += g_m[g_Dlist[j] * CODEN + f];
    float dinv = (t > s) ? 1.f / (float)(t - s) : 0.f;
    float v = acc * dinv + bias[f];
    hid[n * CODEN + f] = v;
    code[n * CODEN + f] = tanhf(v);
}

// ---------------- launch ----------------
extern "C" void kernel_launch(void* const* d_in, const int* in_sizes, int n_in,
                              void* d_out, int out_size) {
    const float* x     = (const float*)d_in[0];
    const float* W1    = (const float*)d_in[1];
    const float* b1    = (const float*)d_in[2];
    const float* theta = (const float*)d_in[3];
    const float* bias  = (const float*)d_in[4];
    const int*   hidx  = (const int*)d_in[5];
    const int* node = hidx;
    const int* edge = hidx + EE;

    float* out  = (float*)d_out;
    float* feat = out;
    float* hid  = out + (size_t)NN * HIDN;
    float* code = hid + (size_t)NN * CODEN;

    zero_kernel<<<(NN * CODEN + 255) / 256, 256>>>();
    round_x_h<<<(NN * (KP / 2) + 255) / 256, 256>>>(x);
    round_wt_h<<<dim3(KP / 32, HIDN / 32), dim3(32, 8)>>>(W1);
    round_th_h<<<dim3(HIDN / 32, CODEN / 32), dim3(32, 8)>>>(theta);
    degree_kernel<<<(EE + 255) / 256, 256>>>(node, edge);
    scan_kernel<<<2, 1024>>>();
    fill_kernel<<<(EE + 255) / 256, 256>>>(node, edge);
    gemm1_h<<<dim3(HIDN / 128, NN / 128), 256>>>(b1, feat);
    gemm2_h<<<dim3(4, NN / 128), 256>>>();
    gather1_kernel<<<NN / 4, 256>>>();
    gather2_kernel<<<NN / 4, 256>>>(hid, code, bias);
}